// round 16
// baseline (speedup 1.0000x reference)
#include <cuda_runtime.h>
#include <cuda_fp16.h>
#include <cstdint>

typedef unsigned long long ull;

// Problem constants
constexpr int NN = 100000;
constexpr int EE = 1250000;
constexpr int KTOT = 576;                 // 64 (root) + 8*64
constexpr int NK = NN * 8;                // (dst, rel) keys
constexpr int NBLK2 = (NK + 1023) / 1024; // 782 scan blocks
constexpr int NCH = 9;                    // 1 root chunk + 8 relation chunks
constexpr int AS = 72;                    // fp16 A/B smem row stride (144 B)
constexpr int EGRID = (EE + 255) / 256;   // 4883
constexpr int PG1 = (64 * KTOT) / 256;    // 144 blocks for W1 prep
constexpr int PG2 = (32 * KTOT) / 256;    // 72 blocks for W2 prep
constexpr int XG = (NN * 64) / (256 * 8); // 3125 blocks for x->fp16 convert

// ---------------- scratch ---------------------------------------------------
__device__ int g_cnt[NK];                 // zero at load; re-zeroed by k_scan
__device__ int g_rowptr[NK + 1];          // +1 sentinel (= EE)
__device__ int g_cursor[NK];
__device__ int g_epack[EE];               // src | (et<<17), sorted by (dst, rel)
__device__ unsigned int g_scanflag[NBLK2];
__device__ __half g_x16[(size_t)NN * 64]; // fp16 input features
__device__ __half g_H[(size_t)NN * 64];   // fp16 hidden layer
__device__ __half g_Agg[(size_t)NN * 512];// fp16 per-relation mean aggregates
__device__ __half g_Wt1[64 * KTOT];       // fp16 transposed [root1|W1]
__device__ __half g_Wt2[32 * KTOT];       // fp16 transposed [root2|W2]

// ---------------- helpers ---------------------------------------------------
__device__ __forceinline__ uint32_t smem_u32(const void* p) {
    uint32_t a;
    asm("{ .reg .u64 t; cvta.to.shared.u64 t, %1; cvt.u32.u64 %0, t; }" : "=r"(a) : "l"(p));
    return a;
}
__device__ __forceinline__ void sts128(uint32_t a, uint32_t x, uint32_t y, uint32_t z, uint32_t w) {
    asm volatile("st.shared.v4.b32 [%0], {%1,%2,%3,%4};" :: "r"(a), "r"(x), "r"(y), "r"(z), "r"(w) : "memory");
}
__device__ __forceinline__ uint32_t lds32(uint32_t a) {
    uint32_t v;
    asm volatile("ld.shared.b32 %0, [%1];" : "=r"(v) : "r"(a));
    return v;
}
__device__ __forceinline__ uint32_t cvt2h(float lo, float hi) {
    uint32_t r;
    asm("cvt.rn.satfinite.f16x2.f32 %0, %1, %2;" : "=r"(r) : "f"(hi), "f"(lo));
    return r;
}
__device__ __forceinline__ void ldmx4(uint32_t* r, uint32_t a) {
    asm volatile("ldmatrix.sync.aligned.m8n8.x4.shared.b16 {%0,%1,%2,%3}, [%4];"
                 : "=r"(r[0]), "=r"(r[1]), "=r"(r[2]), "=r"(r[3]) : "r"(a));
}
__device__ __forceinline__ void mma16816(float* c, const uint32_t* a, uint32_t b0, uint32_t b1) {
    asm volatile("mma.sync.aligned.m16n8k16.row.col.f32.f16.f16.f32 "
                 "{%0,%1,%2,%3}, {%4,%5,%6,%7}, {%8,%9}, {%0,%1,%2,%3};"
                 : "+f"(c[0]), "+f"(c[1]), "+f"(c[2]), "+f"(c[3])
                 : "r"(a[0]), "r"(a[1]), "r"(a[2]), "r"(a[3]), "r"(b0), "r"(b1));
}

// ---------------- CSR build over keys (dst*8 + rel) --------------------------
__global__ void k_count(const int* __restrict__ dst, const int* __restrict__ et) {
    int e = blockIdx.x * blockDim.x + threadIdx.x;
    if (e < NBLK2) g_scanflag[e] = 0;
    if (e < EE) atomicAdd(&g_cnt[dst[e] * 8 + et[e]], 1);
}

__global__ void k_scan() {
    int t = threadIdx.x, b = blockIdx.x, i = b * 1024 + t;
    int lane = t & 31, wid = t >> 5;
    int orig = 0;
    if (i < NK) {
        orig = g_cnt[i];
        g_cnt[i] = 0;
    }
    int v = orig;
#pragma unroll
    for (int o = 1; o < 32; o <<= 1) {
        int nv = __shfl_up_sync(0xffffffffu, v, o);
        if (lane >= o) v += nv;
    }
    __shared__ int ws[32];
    __shared__ int s_prefix;
    if (lane == 31) ws[wid] = v;
    __syncthreads();
    if (wid == 0) {
        int wv = ws[lane];
#pragma unroll
        for (int o = 1; o < 32; o <<= 1) {
            int nv = __shfl_up_sync(0xffffffffu, wv, o);
            if (lane >= o) wv += nv;
        }
        ws[lane] = wv;
    }
    __syncthreads();
    int wpre = wid ? ws[wid - 1] : 0;
    int incl = wpre + v;
    if (t == 0) {
        int total = ws[31];
        if (b == 0) {
            atomicExch(&g_scanflag[0], ((unsigned)total << 2) | 2u);
            s_prefix = 0;
        } else {
            atomicExch(&g_scanflag[b], ((unsigned)total << 2) | 1u);
            int prefix = 0;
            for (int pb = b - 1;;) {
                unsigned wv;
                do { wv = atomicAdd(&g_scanflag[pb], 0u); } while ((wv & 3u) == 0u);
                prefix += (int)(wv >> 2);
                if ((wv & 3u) == 2u) break;
                pb--;
            }
            atomicExch(&g_scanflag[b], ((unsigned)(prefix + total) << 2) | 2u);
            s_prefix = prefix;
        }
    }
    __syncthreads();
    int prefix = s_prefix;
    if (i < NK) {
        int rv = prefix + incl - orig;
        g_rowptr[i] = rv;
        g_cursor[i] = rv;
    }
    if (i == 0) g_rowptr[NK] = EE;
}

// ------- merged: edge build + W transpose (fp16) + x -> fp16 convert ---------
__device__ __forceinline__ void prep_one(const float* __restrict__ root,
                                         const float* __restrict__ W,
                                         __half* __restrict__ oh,
                                         int dout, int i) {
    int n = i / KTOT, k = i % KTOT;
    float v = (k < 64) ? root[k * dout + n] : W[(size_t)(k - 64) * dout + n];
    oh[i] = __float2half_rn(v);
}
__global__ void k_build_prep(const int* __restrict__ src, const int* __restrict__ dst,
                             const int* __restrict__ et, const float* __restrict__ x,
                             const float* __restrict__ root1, const float* __restrict__ W1,
                             const float* __restrict__ root2, const float* __restrict__ W2) {
    int b = blockIdx.x;
    if (b < EGRID) {
        int e = b * 256 + threadIdx.x;
        if (e < EE) {
            int r = et[e];
            int p = atomicAdd(&g_cursor[dst[e] * 8 + r], 1);
            g_epack[p] = src[e] | (r << 17);   // NN < 2^17
        }
    } else if (b < EGRID + XG) {
        size_t i = ((size_t)(b - EGRID) * 256 + threadIdx.x) * 8;
        const float4* xp = reinterpret_cast<const float4*>(x + i);
        float4 v0 = xp[0], v1 = xp[1];
        uint4 o;
        o.x = cvt2h(v0.x, v0.y);
        o.y = cvt2h(v0.z, v0.w);
        o.z = cvt2h(v1.x, v1.y);
        o.w = cvt2h(v1.z, v1.w);
        *reinterpret_cast<uint4*>(g_x16 + i) = o;
    } else if (b < EGRID + XG + PG1) {
        prep_one(root1, W1, g_Wt1, 64, (b - EGRID - XG) * 256 + threadIdx.x);
    } else {
        prep_one(root2, W2, g_Wt2, 32, (b - EGRID - XG - PG1) * 256 + threadIdx.x);
    }
}

// ---------------- aggregation: flattened-stream gather -----------------------
// Each lane owns 2 nodes (8 nodes/warp, 8 lanes per node covering 16 B of the
// 128 B fp16 row). A node's edges across ALL 8 relations are contiguous in
// the (dst,rel)-sorted CSR; relation is packed in the record. Accumulate in
// fp32 registers, flush-on-relation-change (run length = divisor). Missing
// relations covered by pre-zeroed Agg rows. High occupancy: 4 CTAs/SM.
__global__ __launch_bounds__(256, 4) void k_agg(const __half* __restrict__ F,
                                                __half* __restrict__ Agg) {
    int tid = threadIdx.x, w = tid >> 5, l = tid & 31;
    int jl = l & 7, ns = l >> 3;
    int nb = blockIdx.x * 64 + w * 8;

    int mg[2], st[2], deg[2];
#pragma unroll
    for (int p = 0; p < 2; p++) {
        mg[p] = nb + p * 4 + ns;
        if (mg[p] < NN) {
            int s0 = __ldg(g_rowptr + mg[p] * 8);
            st[p] = s0;
            deg[p] = __ldg(g_rowptr + mg[p] * 8 + 8) - s0;
        } else {
            st[p] = 0;
            deg[p] = 0;
        }
    }

    // pre-zero both nodes' Agg rows (this lane's 16-B column segment x 8 rels)
#pragma unroll
    for (int p = 0; p < 2; p++) {
        if (mg[p] < NN) {
            uint4* zp = reinterpret_cast<uint4*>(Agg + (size_t)mg[p] * 512 + jl * 8);
#pragma unroll
            for (int r = 0; r < 8; r++) zp[r * 8] = make_uint4(0u, 0u, 0u, 0u);
        }
    }

    int mx = max(deg[0], deg[1]);
    if (mx == 0) return;

    float4 a0[2], a1[2];
    int rec[2], cur[2], cnt[2];
#pragma unroll
    for (int p = 0; p < 2; p++) {
        a0[p] = make_float4(0.f, 0.f, 0.f, 0.f);
        a1[p] = make_float4(0.f, 0.f, 0.f, 0.f);
        rec[p] = (deg[p] > 0) ? __ldg(g_epack + st[p]) : -1;
        cur[p] = (rec[p] >= 0) ? ((rec[p] >> 17) & 7) : 0;
        cnt[p] = 0;
    }

    for (int j = 0; j < mx; j++) {
        uint4 v[2];
#pragma unroll
        for (int p = 0; p < 2; p++) {
            if (j < deg[p]) {
                int srci = rec[p] & 0x1FFFF;
                v[p] = *(reinterpret_cast<const uint4*>(F + (size_t)srci * 64) + jl);
            }
        }
#pragma unroll
        for (int p = 0; p < 2; p++) {
            int nr = (j + 1 < deg[p]) ? __ldg(g_epack + st[p] + j + 1) : -1;
            if (j < deg[p]) {
                int rl = (rec[p] >> 17) & 7;
                if (rl != cur[p]) {
                    // flush completed run (cnt > 0 guaranteed)
                    float inv = 1.0f / (float)cnt[p];
                    uint4 o;
                    o.x = cvt2h(a0[p].x * inv, a0[p].y * inv);
                    o.y = cvt2h(a0[p].z * inv, a0[p].w * inv);
                    o.z = cvt2h(a1[p].x * inv, a1[p].y * inv);
                    o.w = cvt2h(a1[p].z * inv, a1[p].w * inv);
                    *(reinterpret_cast<uint4*>(Agg + (size_t)mg[p] * 512 + cur[p] * 64 + jl * 8)) = o;
                    a0[p] = make_float4(0.f, 0.f, 0.f, 0.f);
                    a1[p] = make_float4(0.f, 0.f, 0.f, 0.f);
                    cnt[p] = 0;
                    cur[p] = rl;
                }
                float2 f0 = __half22float2(*reinterpret_cast<__half2*>(&v[p].x));
                float2 f1 = __half22float2(*reinterpret_cast<__half2*>(&v[p].y));
                float2 f2 = __half22float2(*reinterpret_cast<__half2*>(&v[p].z));
                float2 f3 = __half22float2(*reinterpret_cast<__half2*>(&v[p].w));
                a0[p].x += f0.x; a0[p].y += f0.y;
                a0[p].z += f1.x; a0[p].w += f1.y;
                a1[p].x += f2.x; a1[p].y += f2.y;
                a1[p].z += f3.x; a1[p].w += f3.y;
                cnt[p]++;
            }
            rec[p] = nr;
        }
    }
    // final flush
#pragma unroll
    for (int p = 0; p < 2; p++) {
        if (cnt[p] > 0) {
            float inv = 1.0f / (float)cnt[p];
            uint4 o;
            o.x = cvt2h(a0[p].x * inv, a0[p].y * inv);
            o.y = cvt2h(a0[p].z * inv, a0[p].w * inv);
            o.z = cvt2h(a1[p].x * inv, a1[p].y * inv);
            o.w = cvt2h(a1[p].z * inv, a1[p].w * inv);
            *(reinterpret_cast<uint4*>(Agg + (size_t)mg[p] * 512 + cur[p] * 64 + jl * 8)) = o;
        }
    }
}

// -------- lean tiled GEMM (single fp16 pass): out = act(bias + [F|Agg]@Wt^T) -
template <int DOUT, bool RELU, bool OUT16>
__global__ __launch_bounds__(256, 3) void k_gemm(
    const __half* __restrict__ F, const __half* __restrict__ Agg,
    const __half* __restrict__ Wt,
    const float* __restrict__ bias, void* __restrict__ outv) {
    constexpr int NT = DOUT / 8;
    constexpr int BP = 256 / DOUT;          // threads per B row
    constexpr int BV = (64 * 2 / BP) / 16;  // uint4 per thread

    extern __shared__ __align__(16) char dyn[];
    uint32_t sA = smem_u32(dyn);
    uint32_t sB = sA + 128 * AS * 2;

    int tid = threadIdx.x;
    int w = tid >> 5, l = tid & 31;
    int m0 = blockIdx.x * 128;

    int jl = l & 7, ns = l >> 3;

    int bn = tid % DOUT, bpart = tid / DOUT;
    uint4 b4[BV];
    auto loadB = [&](int c) {
        size_t off = (size_t)bn * KTOT + c * 64;
        const uint4* bp = reinterpret_cast<const uint4*>(Wt + off) + bpart * BV;
#pragma unroll
        for (int v = 0; v < BV; v++) b4[v] = bp[v];
    };
    auto storeB = [&]() {
        uint32_t bbase = (uint32_t)(bn * (AS * 2) + bpart * (BV * 16));
#pragma unroll
        for (int v = 0; v < BV; v++)
            sts128(sB + bbase + v * 16, b4[v].x, b4[v].y, b4[v].z, b4[v].w);
    };

    uint4 av[4];
    auto loadA = [&](int c) {
#pragma unroll
        for (int p = 0; p < 4; p++) {
            int mg = m0 + w * 16 + p * 4 + ns;
            if (mg < NN) {
                const __half* base = (c == 0) ? (F + (size_t)mg * 64)
                                              : (Agg + (size_t)mg * 512 + (c - 1) * 64);
                av[p] = *(reinterpret_cast<const uint4*>(base) + jl);
            } else {
                av[p] = make_uint4(0u, 0u, 0u, 0u);
            }
        }
    };
    auto storeA = [&]() {
#pragma unroll
        for (int p = 0; p < 4; p++) {
            int nrow = w * 16 + p * 4 + ns;
            sts128(sA + (uint32_t)(nrow * (AS * 2)) + jl * 16,
                   av[p].x, av[p].y, av[p].z, av[p].w);
        }
    };

    float acc[NT][4];
#pragma unroll
    for (int t = 0; t < NT; t++)
#pragma unroll
        for (int q = 0; q < 4; q++) acc[t][q] = 0.f;

    int lrow = w * 16 + (l & 7) + ((l >> 3) & 1) * 8;
    uint32_t aoff = (uint32_t)(lrow * (AS * 2)) + ((l >> 4) & 1) * 16;
    int bfn = l >> 2;
    int bfk = (l & 3) * 4;

    loadB(0);
    loadA(0);
    for (int c = 0; c < NCH; c++) {
        storeB();
        storeA();
        __syncthreads();
        if (c + 1 < NCH) { loadB(c + 1); loadA(c + 1); }
#pragma unroll
        for (int ks = 0; ks < 4; ks++) {
            uint32_t fa[4];
            ldmx4(fa, sA + aoff + ks * 32);
#pragma unroll
            for (int t = 0; t < NT; t++) {
                uint32_t ba = (uint32_t)((t * 8 + bfn) * (AS * 2)) + ks * 32 + bfk;
                uint32_t b0 = lds32(sB + ba), b1 = lds32(sB + ba + 16);
                mma16816(acc[t], fa, b0, b1);
            }
        }
        __syncthreads();
    }

    int r0 = m0 + w * 16 + (l >> 2);
    int cb = (l & 3) * 2;
#pragma unroll
    for (int t = 0; t < NT; t++) {
        int n = t * 8 + cb;
        float b0 = __ldg(bias + n), b1 = __ldg(bias + n + 1);
        float v0 = acc[t][0] + b0, v1 = acc[t][1] + b1;
        float v2 = acc[t][2] + b0, v3 = acc[t][3] + b1;
        if (RELU) {
            v0 = fmaxf(v0, 0.f); v1 = fmaxf(v1, 0.f);
            v2 = fmaxf(v2, 0.f); v3 = fmaxf(v3, 0.f);
        }
        if (OUT16) {
            __half* o16 = reinterpret_cast<__half*>(outv);
            if (r0 < NN)
                *reinterpret_cast<uint32_t*>(o16 + (size_t)r0 * DOUT + n) = cvt2h(v0, v1);
            if (r0 + 8 < NN)
                *reinterpret_cast<uint32_t*>(o16 + (size_t)(r0 + 8) * DOUT + n) = cvt2h(v2, v3);
        } else {
            float* of = reinterpret_cast<float*>(outv);
            if (r0 < NN)
                *reinterpret_cast<float2*>(of + (size_t)r0 * DOUT + n) = make_float2(v0, v1);
            if (r0 + 8 < NN)
                *reinterpret_cast<float2*>(of + (size_t)(r0 + 8) * DOUT + n) = make_float2(v2, v3);
        }
    }
}

// ---------------- launch ----------------------------------------------------
extern "C" void kernel_launch(void* const* d_in, const int* in_sizes, int n_in,
                              void* d_out, int out_size) {
    const float* x     = (const float*)d_in[0];
    const float* W1    = (const float*)d_in[1];
    const float* root1 = (const float*)d_in[2];
    const float* b1    = (const float*)d_in[3];
    const float* W2    = (const float*)d_in[4];
    const float* root2 = (const float*)d_in[5];
    const float* b2    = (const float*)d_in[6];
    const int*   src   = (const int*)d_in[7];
    const int*   dst   = (const int*)d_in[8];
    const int*   et    = (const int*)d_in[9];

    __half *H, *x16, *Agg, *w1, *w2;
    cudaGetSymbolAddress((void**)&H, g_H);
    cudaGetSymbolAddress((void**)&x16, g_x16);
    cudaGetSymbolAddress((void**)&Agg, g_Agg);
    cudaGetSymbolAddress((void**)&w1, g_Wt1);
    cudaGetSymbolAddress((void**)&w2, g_Wt2);

    const int ggrid = (NN + 127) / 128;
    const int agrid = (NN + 63) / 64;
    const int smA = 128 * AS * 2;
    const int smem64 = smA + 64 * AS * 2;   // 27648
    const int smem32 = smA + 32 * AS * 2;   // 23040

    static bool attr_done = false;
    if (!attr_done) {
        cudaFuncSetAttribute(k_gemm<64, true, true>,
                             cudaFuncAttributeMaxDynamicSharedMemorySize, smem64);
        cudaFuncSetAttribute(k_gemm<32, false, false>,
                             cudaFuncAttributeMaxDynamicSharedMemorySize, smem32);
        attr_done = true;
    }

    // CSR build over (dst, rel) keys (g_cnt pre-zeroed by previous call's k_scan)
    k_count<<<EGRID, 256>>>(dst, et);
    k_scan<<<NBLK2, 1024>>>();
    k_build_prep<<<EGRID + XG + PG1 + PG2, 256>>>(src, dst, et, x,
                                                  root1, W1, root2, W2);

    // Layer 1: aggregate then GEMM (H written fp16)
    k_agg<<<agrid, 256>>>(x16, Agg);
    k_gemm<64, true, true><<<ggrid, 256, smem64>>>(x16, Agg, w1, b1, H);

    // Layer 2: aggregate H then GEMM -> fp32 output
    k_agg<<<agrid, 256>>>(H, Agg);
    k_gemm<32, false, false><<<ggrid, 256, smem32>>>(H, Agg, w2, b2, d_out);
}

// round 17
// speedup vs baseline: 1.0605x; 1.0605x over previous
#include <cuda_runtime.h>
#include <cuda_fp16.h>
#include <cstdint>

typedef unsigned long long ull;

// Problem constants
constexpr int NN = 100000;
constexpr int EE = 1250000;
constexpr int KTOT = 576;                 // 64 (root) + 8*64
constexpr int NK = NN * 8;                // (dst, rel) keys
constexpr int NBLK2 = (NK + 1023) / 1024; // 782 scan blocks
constexpr int NCH = 9;                    // 1 root chunk + 8 relation chunks
constexpr int AS = 72;                    // fp16 A/B smem row stride (144 B)
constexpr int EGRID = (EE + 255) / 256;   // 4883
constexpr int PG1 = (64 * KTOT) / 256;    // 144 blocks for W1 prep
constexpr int PG2 = (32 * KTOT) / 256;    // 72 blocks for W2 prep
constexpr int XG = (NN * 64) / (256 * 8); // 3125 blocks for x->fp16 convert

// ---------------- scratch ---------------------------------------------------
__device__ int g_cnt[NK];                 // zero at load; re-zeroed by k_scan
__device__ int g_rowptr[NK + 1];          // +1 sentinel (= EE)
__device__ int g_cursor[NK];
__device__ int g_epack[EE];               // src | (et<<17), sorted by (dst, rel)
__device__ unsigned int g_scanflag[NBLK2];
__device__ __half g_x16[(size_t)NN * 64]; // fp16 input features
__device__ __half g_H[(size_t)NN * 64];   // fp16 hidden layer
__device__ __half g_Agg[(size_t)NN * 512];// fp16 per-relation mean aggregates
__device__ __half g_Wt1[64 * KTOT];       // fp16 transposed [root1|W1]
__device__ __half g_Wt2[32 * KTOT];       // fp16 transposed [root2|W2]

// ---------------- helpers ---------------------------------------------------
__device__ __forceinline__ uint32_t smem_u32(const void* p) {
    uint32_t a;
    asm("{ .reg .u64 t; cvta.to.shared.u64 t, %1; cvt.u32.u64 %0, t; }" : "=r"(a) : "l"(p));
    return a;
}
__device__ __forceinline__ void sts128(uint32_t a, uint32_t x, uint32_t y, uint32_t z, uint32_t w) {
    asm volatile("st.shared.v4.b32 [%0], {%1,%2,%3,%4};" :: "r"(a), "r"(x), "r"(y), "r"(z), "r"(w) : "memory");
}
__device__ __forceinline__ uint32_t lds32(uint32_t a) {
    uint32_t v;
    asm volatile("ld.shared.b32 %0, [%1];" : "=r"(v) : "r"(a));
    return v;
}
__device__ __forceinline__ uint32_t cvt2h(float lo, float hi) {
    uint32_t r;
    asm("cvt.rn.satfinite.f16x2.f32 %0, %1, %2;" : "=r"(r) : "f"(hi), "f"(lo));
    return r;
}
__device__ __forceinline__ void ldmx4(uint32_t* r, uint32_t a) {
    asm volatile("ldmatrix.sync.aligned.m8n8.x4.shared.b16 {%0,%1,%2,%3}, [%4];"
                 : "=r"(r[0]), "=r"(r[1]), "=r"(r[2]), "=r"(r[3]) : "r"(a));
}
__device__ __forceinline__ void mma16816(float* c, const uint32_t* a, uint32_t b0, uint32_t b1) {
    asm volatile("mma.sync.aligned.m16n8k16.row.col.f32.f16.f16.f32 "
                 "{%0,%1,%2,%3}, {%4,%5,%6,%7}, {%8,%9}, {%0,%1,%2,%3};"
                 : "+f"(c[0]), "+f"(c[1]), "+f"(c[2]), "+f"(c[3])
                 : "r"(a[0]), "r"(a[1]), "r"(a[2]), "r"(a[3]), "r"(b0), "r"(b1));
}

// ---------------- CSR build over keys (dst*8 + rel) --------------------------
__global__ void k_count(const int* __restrict__ dst, const int* __restrict__ et) {
    int e = blockIdx.x * blockDim.x + threadIdx.x;
    if (e < NBLK2) g_scanflag[e] = 0;
    if (e < EE) atomicAdd(&g_cnt[dst[e] * 8 + et[e]], 1);
}

__global__ void k_scan() {
    int t = threadIdx.x, b = blockIdx.x, i = b * 1024 + t;
    int lane = t & 31, wid = t >> 5;
    int orig = 0;
    if (i < NK) {
        orig = g_cnt[i];
        g_cnt[i] = 0;
    }
    int v = orig;
#pragma unroll
    for (int o = 1; o < 32; o <<= 1) {
        int nv = __shfl_up_sync(0xffffffffu, v, o);
        if (lane >= o) v += nv;
    }
    __shared__ int ws[32];
    __shared__ int s_prefix;
    if (lane == 31) ws[wid] = v;
    __syncthreads();
    if (wid == 0) {
        int wv = ws[lane];
#pragma unroll
        for (int o = 1; o < 32; o <<= 1) {
            int nv = __shfl_up_sync(0xffffffffu, wv, o);
            if (lane >= o) wv += nv;
        }
        ws[lane] = wv;
    }
    __syncthreads();
    int wpre = wid ? ws[wid - 1] : 0;
    int incl = wpre + v;
    if (t == 0) {
        int total = ws[31];
        if (b == 0) {
            atomicExch(&g_scanflag[0], ((unsigned)total << 2) | 2u);
            s_prefix = 0;
        } else {
            atomicExch(&g_scanflag[b], ((unsigned)total << 2) | 1u);
            int prefix = 0;
            for (int pb = b - 1;;) {
                unsigned wv;
                do { wv = atomicAdd(&g_scanflag[pb], 0u); } while ((wv & 3u) == 0u);
                prefix += (int)(wv >> 2);
                if ((wv & 3u) == 2u) break;
                pb--;
            }
            atomicExch(&g_scanflag[b], ((unsigned)(prefix + total) << 2) | 2u);
            s_prefix = prefix;
        }
    }
    __syncthreads();
    int prefix = s_prefix;
    if (i < NK) {
        int rv = prefix + incl - orig;
        g_rowptr[i] = rv;
        g_cursor[i] = rv;
    }
    if (i == 0) g_rowptr[NK] = EE;
}

// ------- merged: edge build + W transpose (fp16) + x -> fp16 convert ---------
__device__ __forceinline__ void prep_one(const float* __restrict__ root,
                                         const float* __restrict__ W,
                                         __half* __restrict__ oh,
                                         int dout, int i) {
    int n = i / KTOT, k = i % KTOT;
    float v = (k < 64) ? root[k * dout + n] : W[(size_t)(k - 64) * dout + n];
    oh[i] = __float2half_rn(v);
}
__global__ void k_build_prep(const int* __restrict__ src, const int* __restrict__ dst,
                             const int* __restrict__ et, const float* __restrict__ x,
                             const float* __restrict__ root1, const float* __restrict__ W1,
                             const float* __restrict__ root2, const float* __restrict__ W2) {
    int b = blockIdx.x;
    if (b < EGRID) {
        int e = b * 256 + threadIdx.x;
        if (e < EE) {
            int r = et[e];
            int p = atomicAdd(&g_cursor[dst[e] * 8 + r], 1);
            g_epack[p] = src[e] | (r << 17);   // NN < 2^17
        }
    } else if (b < EGRID + XG) {
        size_t i = ((size_t)(b - EGRID) * 256 + threadIdx.x) * 8;
        const float4* xp = reinterpret_cast<const float4*>(x + i);
        float4 v0 = xp[0], v1 = xp[1];
        uint4 o;
        o.x = cvt2h(v0.x, v0.y);
        o.y = cvt2h(v0.z, v0.w);
        o.z = cvt2h(v1.x, v1.y);
        o.w = cvt2h(v1.z, v1.w);
        *reinterpret_cast<uint4*>(g_x16 + i) = o;
    } else if (b < EGRID + XG + PG1) {
        prep_one(root1, W1, g_Wt1, 64, (b - EGRID - XG) * 256 + threadIdx.x);
    } else {
        prep_one(root2, W2, g_Wt2, 32, (b - EGRID - XG - PG1) * 256 + threadIdx.x);
    }
}

// ---------------- aggregation: flattened-stream gather, pipelined ------------
// Each lane owns 2 nodes (8 nodes/warp, 8 lanes/node covering 16 B of the
// 128 B fp16 row). Node's edges across all 8 relations are contiguous in the
// (dst,rel)-sorted CSR; rel packed in record. fp32 register accumulation,
// flush-on-relation-change. Value loads software-pipelined one iteration
// ahead (recs two ahead) to hide L2 latency. Each Agg segment written exactly
// once (flushed-bitmask tail covers empty relations).
__global__ __launch_bounds__(256, 3) void k_agg(const __half* __restrict__ F,
                                                __half* __restrict__ Agg) {
    int tid = threadIdx.x, w = tid >> 5, l = tid & 31;
    int jl = l & 7, ns = l >> 3;
    int nb = blockIdx.x * 64 + w * 8;

    int mg[2], st[2], deg[2];
#pragma unroll
    for (int p = 0; p < 2; p++) {
        mg[p] = nb + p * 4 + ns;
        if (mg[p] < NN) {
            int s0 = __ldg(g_rowptr + mg[p] * 8);
            st[p] = s0;
            deg[p] = __ldg(g_rowptr + mg[p] * 8 + 8) - s0;
        } else {
            st[p] = 0;
            deg[p] = 0;
        }
    }

    int mx = max(deg[0], deg[1]);

    float4 a0[2], a1[2];
    int rec0[2], rec1[2], cur[2], cnt[2];
    unsigned flushed[2] = {0u, 0u};
    uint4 v0[2], v1[2];
#pragma unroll
    for (int p = 0; p < 2; p++) {
        a0[p] = make_float4(0.f, 0.f, 0.f, 0.f);
        a1[p] = make_float4(0.f, 0.f, 0.f, 0.f);
        rec0[p] = (deg[p] > 0) ? __ldg(g_epack + st[p]) : -1;
        rec1[p] = (deg[p] > 1) ? __ldg(g_epack + st[p] + 1) : -1;
        cur[p] = (rec0[p] >= 0) ? ((rec0[p] >> 17) & 7) : 0;
        cnt[p] = 0;
    }
#pragma unroll
    for (int p = 0; p < 2; p++) {
        if (rec0[p] >= 0)
            v0[p] = *(reinterpret_cast<const uint4*>(F + (size_t)(rec0[p] & 0x1FFFF) * 64) + jl);
    }

    for (int j = 0; j < mx; j++) {
        // prefetch next value + next-next record
#pragma unroll
        for (int p = 0; p < 2; p++) {
            if (rec1[p] >= 0)
                v1[p] = *(reinterpret_cast<const uint4*>(F + (size_t)(rec1[p] & 0x1FFFF) * 64) + jl);
        }
        int rec2[2];
#pragma unroll
        for (int p = 0; p < 2; p++)
            rec2[p] = (j + 2 < deg[p]) ? __ldg(g_epack + st[p] + j + 2) : -1;
        // process current edge
#pragma unroll
        for (int p = 0; p < 2; p++) {
            if (rec0[p] >= 0) {
                int rl = (rec0[p] >> 17) & 7;
                if (rl != cur[p]) {
                    float inv = 1.0f / (float)cnt[p];
                    uint4 o;
                    o.x = cvt2h(a0[p].x * inv, a0[p].y * inv);
                    o.y = cvt2h(a0[p].z * inv, a0[p].w * inv);
                    o.z = cvt2h(a1[p].x * inv, a1[p].y * inv);
                    o.w = cvt2h(a1[p].z * inv, a1[p].w * inv);
                    *(reinterpret_cast<uint4*>(Agg + (size_t)mg[p] * 512 + cur[p] * 64 + jl * 8)) = o;
                    flushed[p] |= 1u << cur[p];
                    a0[p] = make_float4(0.f, 0.f, 0.f, 0.f);
                    a1[p] = make_float4(0.f, 0.f, 0.f, 0.f);
                    cnt[p] = 0;
                    cur[p] = rl;
                }
                float2 f0 = __half22float2(*reinterpret_cast<__half2*>(&v0[p].x));
                float2 f1 = __half22float2(*reinterpret_cast<__half2*>(&v0[p].y));
                float2 f2 = __half22float2(*reinterpret_cast<__half2*>(&v0[p].z));
                float2 f3 = __half22float2(*reinterpret_cast<__half2*>(&v0[p].w));
                a0[p].x += f0.x; a0[p].y += f0.y;
                a0[p].z += f1.x; a0[p].w += f1.y;
                a1[p].x += f2.x; a1[p].y += f2.y;
                a1[p].z += f3.x; a1[p].w += f3.y;
                cnt[p]++;
            }
            rec0[p] = rec1[p];
            rec1[p] = rec2[p];
            v0[p] = v1[p];
        }
    }
    // final flush + zero-fill untouched relation segments
#pragma unroll
    for (int p = 0; p < 2; p++) {
        if (cnt[p] > 0) {
            float inv = 1.0f / (float)cnt[p];
            uint4 o;
            o.x = cvt2h(a0[p].x * inv, a0[p].y * inv);
            o.y = cvt2h(a0[p].z * inv, a0[p].w * inv);
            o.z = cvt2h(a1[p].x * inv, a1[p].y * inv);
            o.w = cvt2h(a1[p].z * inv, a1[p].w * inv);
            *(reinterpret_cast<uint4*>(Agg + (size_t)mg[p] * 512 + cur[p] * 64 + jl * 8)) = o;
            flushed[p] |= 1u << cur[p];
        }
        if (mg[p] < NN) {
            uint4* zp = reinterpret_cast<uint4*>(Agg + (size_t)mg[p] * 512 + jl * 8);
#pragma unroll
            for (int r = 0; r < 8; r++)
                if (!((flushed[p] >> r) & 1u)) zp[r * 8] = make_uint4(0u, 0u, 0u, 0u);
        }
    }
}

// -------- lean tiled GEMM (single fp16 pass): out = act(bias + [F|Agg]@Wt^T) -
template <int DOUT, bool RELU, bool OUT16>
__global__ __launch_bounds__(256, 3) void k_gemm(
    const __half* __restrict__ F, const __half* __restrict__ Agg,
    const __half* __restrict__ Wt,
    const float* __restrict__ bias, void* __restrict__ outv) {
    constexpr int NT = DOUT / 8;
    constexpr int BP = 256 / DOUT;          // threads per B row
    constexpr int BV = (64 * 2 / BP) / 16;  // uint4 per thread

    extern __shared__ __align__(16) char dyn[];
    uint32_t sA = smem_u32(dyn);
    uint32_t sB = sA + 128 * AS * 2;

    int tid = threadIdx.x;
    int w = tid >> 5, l = tid & 31;
    int m0 = blockIdx.x * 128;

    int jl = l & 7, ns = l >> 3;

    int bn = tid % DOUT, bpart = tid / DOUT;
    uint4 b4[BV];
    auto loadB = [&](int c) {
        size_t off = (size_t)bn * KTOT + c * 64;
        const uint4* bp = reinterpret_cast<const uint4*>(Wt + off) + bpart * BV;
#pragma unroll
        for (int v = 0; v < BV; v++) b4[v] = bp[v];
    };
    auto storeB = [&]() {
        uint32_t bbase = (uint32_t)(bn * (AS * 2) + bpart * (BV * 16));
#pragma unroll
        for (int v = 0; v < BV; v++)
            sts128(sB + bbase + v * 16, b4[v].x, b4[v].y, b4[v].z, b4[v].w);
    };

    uint4 av[4];
    auto loadA = [&](int c) {
#pragma unroll
        for (int p = 0; p < 4; p++) {
            int mg = m0 + w * 16 + p * 4 + ns;
            if (mg < NN) {
                const __half* base = (c == 0) ? (F + (size_t)mg * 64)
                                              : (Agg + (size_t)mg * 512 + (c - 1) * 64);
                av[p] = *(reinterpret_cast<const uint4*>(base) + jl);
            } else {
                av[p] = make_uint4(0u, 0u, 0u, 0u);
            }
        }
    };
    auto storeA = [&]() {
#pragma unroll
        for (int p = 0; p < 4; p++) {
            int nrow = w * 16 + p * 4 + ns;
            sts128(sA + (uint32_t)(nrow * (AS * 2)) + jl * 16,
                   av[p].x, av[p].y, av[p].z, av[p].w);
        }
    };

    float acc[NT][4];
#pragma unroll
    for (int t = 0; t < NT; t++)
#pragma unroll
        for (int q = 0; q < 4; q++) acc[t][q] = 0.f;

    int lrow = w * 16 + (l & 7) + ((l >> 3) & 1) * 8;
    uint32_t aoff = (uint32_t)(lrow * (AS * 2)) + ((l >> 4) & 1) * 16;
    int bfn = l >> 2;
    int bfk = (l & 3) * 4;

    loadB(0);
    loadA(0);
    for (int c = 0; c < NCH; c++) {
        storeB();
        storeA();
        __syncthreads();
        if (c + 1 < NCH) { loadB(c + 1); loadA(c + 1); }
#pragma unroll
        for (int ks = 0; ks < 4; ks++) {
            uint32_t fa[4];
            ldmx4(fa, sA + aoff + ks * 32);
#pragma unroll
            for (int t = 0; t < NT; t++) {
                uint32_t ba = (uint32_t)((t * 8 + bfn) * (AS * 2)) + ks * 32 + bfk;
                uint32_t b0 = lds32(sB + ba), b1 = lds32(sB + ba + 16);
                mma16816(acc[t], fa, b0, b1);
            }
        }
        __syncthreads();
    }

    int r0 = m0 + w * 16 + (l >> 2);
    int cb = (l & 3) * 2;
#pragma unroll
    for (int t = 0; t < NT; t++) {
        int n = t * 8 + cb;
        float b0 = __ldg(bias + n), b1 = __ldg(bias + n + 1);
        float v0 = acc[t][0] + b0, v1 = acc[t][1] + b1;
        float v2 = acc[t][2] + b0, v3 = acc[t][3] + b1;
        if (RELU) {
            v0 = fmaxf(v0, 0.f); v1 = fmaxf(v1, 0.f);
            v2 = fmaxf(v2, 0.f); v3 = fmaxf(v3, 0.f);
        }
        if (OUT16) {
            __half* o16 = reinterpret_cast<__half*>(outv);
            if (r0 < NN)
                *reinterpret_cast<uint32_t*>(o16 + (size_t)r0 * DOUT + n) = cvt2h(v0, v1);
            if (r0 + 8 < NN)
                *reinterpret_cast<uint32_t*>(o16 + (size_t)(r0 + 8) * DOUT + n) = cvt2h(v2, v3);
        } else {
            float* of = reinterpret_cast<float*>(outv);
            if (r0 < NN)
                *reinterpret_cast<float2*>(of + (size_t)r0 * DOUT + n) = make_float2(v0, v1);
            if (r0 + 8 < NN)
                *reinterpret_cast<float2*>(of + (size_t)(r0 + 8) * DOUT + n) = make_float2(v2, v3);
        }
    }
}

// ---------------- launch ----------------------------------------------------
extern "C" void kernel_launch(void* const* d_in, const int* in_sizes, int n_in,
                              void* d_out, int out_size) {
    const float* x     = (const float*)d_in[0];
    const float* W1    = (const float*)d_in[1];
    const float* root1 = (const float*)d_in[2];
    const float* b1    = (const float*)d_in[3];
    const float* W2    = (const float*)d_in[4];
    const float* root2 = (const float*)d_in[5];
    const float* b2    = (const float*)d_in[6];
    const int*   src   = (const int*)d_in[7];
    const int*   dst   = (const int*)d_in[8];
    const int*   et    = (const int*)d_in[9];

    __half *H, *x16, *Agg, *w1, *w2;
    cudaGetSymbolAddress((void**)&H, g_H);
    cudaGetSymbolAddress((void**)&x16, g_x16);
    cudaGetSymbolAddress((void**)&Agg, g_Agg);
    cudaGetSymbolAddress((void**)&w1, g_Wt1);
    cudaGetSymbolAddress((void**)&w2, g_Wt2);

    const int ggrid = (NN + 127) / 128;
    const int agrid = (NN + 63) / 64;
    const int smA = 128 * AS * 2;
    const int smem64 = smA + 64 * AS * 2;   // 27648
    const int smem32 = smA + 32 * AS * 2;   // 23040

    static bool attr_done = false;
    if (!attr_done) {
        cudaFuncSetAttribute(k_gemm<64, true, true>,
                             cudaFuncAttributeMaxDynamicSharedMemorySize, smem64);
        cudaFuncSetAttribute(k_gemm<32, false, false>,
                             cudaFuncAttributeMaxDynamicSharedMemorySize, smem32);
        attr_done = true;
    }

    // CSR build over (dst, rel) keys (g_cnt pre-zeroed by previous call's k_scan)
    k_count<<<EGRID, 256>>>(dst, et);
    k_scan<<<NBLK2, 1024>>>();
    k_build_prep<<<EGRID + XG + PG1 + PG2, 256>>>(src, dst, et, x,
                                                  root1, W1, root2, W2);

    // Layer 1: aggregate then GEMM (H written fp16)
    k_agg<<<agrid, 256>>>(x16, Agg);
    k_gemm<64, true, true><<<ggrid, 256, smem64>>>(x16, Agg, w1, b1, H);

    // Layer 2: aggregate H then GEMM -> fp32 output
    k_agg<<<agrid, 256>>>(H, Agg);
    k_gemm<32, false, false><<<ggrid, 256, smem32>>>(H, Agg, w2, b2, d_out);
}